// round 12
// baseline (speedup 1.0000x reference)
#include <cuda_runtime.h>
#include <math.h>
#include <stdint.h>

#define THREADS 256
#define ROWS 64
#define LDA 68
#define WLD 72

// ---- shared memory layout (float offsets) ----
#define OFF_ENV 0              // 64 x 68
#define OFF_OWN 4352
#define OFF_A   8704
#define OFF_E1  13056
#define OFF_W   17408          // 64 x 72
#define OFF_B0  22016
#define OFF_BG  22080
#define OFF_BS1 22144
#define OFF_BS2 22208
#define OFF_BC1 22272          // 128
#define OFF_BC2 22400          // 128
#define OFF_BC3 22528          // 4
#define OFF_WS1 22532          // 7x64
#define OFF_WC3 22980          // 128x2
#define OFF_SC  23236          // 64x8
#define OFF_AL  23748          // 64x8
#define OFF_MK  24260          // 64x8
#define SMEM_FLOATS 24772
#define SMEM_BYTES (SMEM_FLOATS * 4)

__device__ float g_e2[(size_t)65536 * 8 * 64];   // e2 spill, L2-hot per CTA
__device__ float g_Wqk[64 * 64];                 // M = Wq @ Wk^T

// round to tf32, keep as fp32 bit pattern
__device__ __forceinline__ float f2tf_f(float x) {
    uint32_t r;
    asm("cvt.rna.tf32.f32 %0, %1;" : "=r"(r) : "f"(x));
    return __uint_as_float(r);
}

__device__ __forceinline__ void mma8(float (&c)[4], uint32_t a0, uint32_t a1,
                                     uint32_t a2, uint32_t a3,
                                     uint32_t b0, uint32_t b1)
{
    asm volatile("mma.sync.aligned.m16n8k8.row.col.f32.tf32.tf32.f32 "
                 "{%0,%1,%2,%3}, {%4,%5,%6,%7}, {%8,%9}, {%0,%1,%2,%3};"
                 : "+f"(c[0]), "+f"(c[1]), "+f"(c[2]), "+f"(c[3])
                 : "r"(a0), "r"(a1), "r"(a2), "r"(a3), "r"(b0), "r"(b1));
}

// warp-level 64x64x64 MMA; operands are PRE-CONVERTED tf32 bits (no cvt here)
__device__ __forceinline__ void mma_k64(const float* __restrict__ A,
                                        const float* __restrict__ W,
                                        int R0, int C0, int gid, int tig,
                                        float (&c)[4][4])
{
#pragma unroll
    for (int kt = 0; kt < 8; ++kt) {
        const float* Ap = A + (R0 + gid) * LDA + kt * 8 + tig;
        uint32_t a0 = __float_as_uint(Ap[0]);
        uint32_t a1 = __float_as_uint(Ap[8 * LDA]);
        uint32_t a2 = __float_as_uint(Ap[4]);
        uint32_t a3 = __float_as_uint(Ap[8 * LDA + 4]);
        const float* Wp = W + (kt * 8 + tig) * WLD + C0 + gid;
#pragma unroll
        for (int j = 0; j < 4; ++j) {
            uint32_t b0 = __float_as_uint(Wp[8 * j]);
            uint32_t b1 = __float_as_uint(Wp[4 * WLD + 8 * j]);
            mma8(c[j], a0, a1, a2, a3, b0, b1);
        }
    }
}

// epilogue: optional bias + relu; cvt -> store tf32 bits for downstream MMA
__device__ __forceinline__ void epi_store(float (&c)[4][4], float* dst,
                                          const float* bias, bool relu, bool cvt,
                                          int R0, int C0, int gid, int tig)
{
#pragma unroll
    for (int j = 0; j < 4; ++j) {
        int cc = C0 + 8 * j + 2 * tig;
        float bx = bias ? bias[cc] : 0.f;
        float by = bias ? bias[cc + 1] : 0.f;
        float2 v0 = make_float2(c[j][0] + bx, c[j][1] + by);
        float2 v1 = make_float2(c[j][2] + bx, c[j][3] + by);
        if (relu) {
            v0.x = fmaxf(v0.x, 0.f); v0.y = fmaxf(v0.y, 0.f);
            v1.x = fmaxf(v1.x, 0.f); v1.y = fmaxf(v1.y, 0.f);
        }
        if (cvt) {
            v0.x = f2tf_f(v0.x); v0.y = f2tf_f(v0.y);
            v1.x = f2tf_f(v1.x); v1.y = f2tf_f(v1.y);
        }
        *(float2*)(dst + (R0 + gid) * LDA + cc) = v0;
        *(float2*)(dst + (R0 + gid + 8) * LDA + cc) = v1;
    }
}

// scalar microkernel for tiny-K GEMMs (K=6,7). A leading dim LDA. fp32 exact.
template<int K, int WL>
__device__ __forceinline__ void mm_small(const float* __restrict__ A,
                                         const float* __restrict__ W,
                                         int r0, int c0, float (&acc)[4][4])
{
#pragma unroll
    for (int k = 0; k < K; ++k) {
        float a0 = A[(r0 + 0) * LDA + k];
        float a1 = A[(r0 + 1) * LDA + k];
        float a2 = A[(r0 + 2) * LDA + k];
        float a3 = A[(r0 + 3) * LDA + k];
        float4 b = *(const float4*)(W + k * WL + c0);
        acc[0][0] = fmaf(a0, b.x, acc[0][0]); acc[0][1] = fmaf(a0, b.y, acc[0][1]);
        acc[0][2] = fmaf(a0, b.z, acc[0][2]); acc[0][3] = fmaf(a0, b.w, acc[0][3]);
        acc[1][0] = fmaf(a1, b.x, acc[1][0]); acc[1][1] = fmaf(a1, b.y, acc[1][1]);
        acc[1][2] = fmaf(a1, b.z, acc[1][2]); acc[1][3] = fmaf(a1, b.w, acc[1][3]);
        acc[2][0] = fmaf(a2, b.x, acc[2][0]); acc[2][1] = fmaf(a2, b.y, acc[2][1]);
        acc[2][2] = fmaf(a2, b.z, acc[2][2]); acc[2][3] = fmaf(a2, b.w, acc[2][3]);
        acc[3][0] = fmaf(a3, b.x, acc[3][0]); acc[3][1] = fmaf(a3, b.y, acc[3][1]);
        acc[3][2] = fmaf(a3, b.z, acc[3][2]); acc[3][3] = fmaf(a3, b.w, acc[3][3]);
    }
}

// register prefetch of a 64x64 weight tile (row stride 'stride' floats)
__device__ __forceinline__ void pf4(float4 (&pw)[4], const float* __restrict__ base,
                                    int stride, int tid)
{
#pragma unroll
    for (int j = 0; j < 4; ++j) {
        int fi = tid + j * 256;
        pw[j] = *(const float4*)(base + (fi >> 4) * stride + (fi & 15) * 4);
    }
}

// write prefetched tile to wS, converting to tf32
__device__ __forceinline__ void wr4(float4 (&pw)[4], float* wS, int tid)
{
#pragma unroll
    for (int j = 0; j < 4; ++j) {
        int fi = tid + j * 256;
        int r = fi >> 4, c4 = (fi & 15) * 4;
        *(float4*)(wS + r * WLD + c4) =
            make_float4(f2tf_f(pw[j].x), f2tf_f(pw[j].y),
                        f2tf_f(pw[j].z), f2tf_f(pw[j].w));
    }
}

__global__ void wqk_kernel(const float* __restrict__ Wq, const float* __restrict__ Wk)
{
    int idx = blockIdx.x * 256 + threadIdx.x;
    int c = idx >> 6, d = idx & 63;
    float s = 0.f;
#pragma unroll 8
    for (int j = 0; j < 64; ++j)
        s = fmaf(Wq[c * 64 + j], Wk[d * 64 + j], s);
    g_Wqk[idx] = s;
}

__global__ void __launch_bounds__(THREADS, 2)
actor_kernel(const float* __restrict__ state0, const float* __restrict__ state1,
             const float* __restrict__ state2,
             const float* __restrict__ W0,  const float* __restrict__ b0,
             const float* __restrict__ Wg,  const float* __restrict__ bg,
             const float* __restrict__ Ws1, const float* __restrict__ bs1,
             const float* __restrict__ Ws2, const float* __restrict__ bs2,
             const float* __restrict__ Wv,
             const float* __restrict__ Wc1, const float* __restrict__ bc1,
             const float* __restrict__ Wc2, const float* __restrict__ bc2,
             const float* __restrict__ Wc3, const float* __restrict__ bc3,
             float* __restrict__ out)
{
    extern __shared__ float sm[];
    const int tid  = threadIdx.x;
    const int lane = tid & 31, wid = tid >> 5;
    const int gid = lane >> 2, tig = lane & 3;
    const int R0 = (wid >> 1) * 16, C0 = (wid & 1) * 32;
    const int tx = tid & 15, ty = tid >> 4;       // scalar-path mapping
    const int r0 = ty * 4, c0 = tx * 4;
    const int row0 = blockIdx.x * ROWS;

    float* envS = sm + OFF_ENV;
    float* ownS = sm + OFF_OWN;
    float* aS   = sm + OFF_A;
    float* e1S  = sm + OFF_E1;
    float* wS   = sm + OFF_W;

    float4 pw[4];   // weight prefetch registers

    // constants
    if (tid < 64) {
        sm[OFF_B0 + tid]  = b0[tid];  sm[OFF_BG + tid]  = bg[tid];
        sm[OFF_BS1 + tid] = bs1[tid]; sm[OFF_BS2 + tid] = bs2[tid];
    }
    if (tid < 128) { sm[OFF_BC1 + tid] = bc1[tid]; sm[OFF_BC2 + tid] = bc2[tid]; }
    if (tid < 2)   { sm[OFF_BC3 + tid] = bc3[tid]; }
    for (int i = tid; i < 448; i += THREADS) sm[OFF_WS1 + i] = Ws1[i];
    for (int i = tid; i < 256; i += THREADS) sm[OFF_WC3 + i] = Wc3[i];

    // ---------- Phase 1: env_e = relu(state1 @ Wg + bg), K=1024, tf32 MMA ----------
    {
        float acc[4][4] = {};
        float4 ra[4], rw[4];
#pragma unroll
        for (int j = 0; j < 4; ++j) {
            int i = tid + j * 256, m = i >> 4, c4 = i & 15;
            ra[j] = *(const float4*)(state1 + (size_t)(row0 + m) * 1024 + c4 * 4);
            rw[j] = *(const float4*)(Wg + (size_t)m * 64 + c4 * 4);
        }
        for (int ch = 0; ch < 16; ++ch) {
#pragma unroll
            for (int j = 0; j < 4; ++j) {
                int i = tid + j * 256, m = i >> 4, c4 = i & 15;
                *(float4*)(aS + m * LDA + c4 * 4) =
                    make_float4(f2tf_f(ra[j].x), f2tf_f(ra[j].y),
                                f2tf_f(ra[j].z), f2tf_f(ra[j].w));
                *(float4*)(wS + m * WLD + c4 * 4) =
                    make_float4(f2tf_f(rw[j].x), f2tf_f(rw[j].y),
                                f2tf_f(rw[j].z), f2tf_f(rw[j].w));
            }
            __syncthreads();
            if (ch + 1 < 16) {
                int kk = (ch + 1) * 64;
#pragma unroll
                for (int j = 0; j < 4; ++j) {
                    int i = tid + j * 256, m = i >> 4, c4 = i & 15;
                    ra[j] = *(const float4*)(state1 + (size_t)(row0 + m) * 1024 + kk + c4 * 4);
                    rw[j] = *(const float4*)(Wg + (size_t)(kk + m) * 64 + c4 * 4);
                }
            }
            mma_k64(aS, wS, R0, C0, gid, tig, acc);
            __syncthreads();
        }
        epi_store(acc, envS, sm + OFF_BG, true, true, R0, C0, gid, tig);
    }

    // ---------- Phase 2: own_e = relu(state0 @ W0 + b0), K=6, scalar fp32 ----------
    for (int i = tid; i < 384; i += THREADS)
        aS[(i / 6) * LDA + (i % 6)] = state0[(size_t)row0 * 6 + i];
    for (int i = tid; i < 384; i += THREADS)
        wS[(i >> 6) * WLD + (i & 63)] = W0[i];
    __syncthreads();
    {
        float acc[4][4] = {};
        mm_small<6, WLD>(aS, wS, r0, c0, acc);
        pf4(pw, g_Wqk, 64, tid);          // prefetch Wqk while FMA runs
#pragma unroll
        for (int i = 0; i < 4; ++i) {
            float4 v;
            v.x = f2tf_f(fmaxf(acc[i][0] + sm[OFF_B0 + c0 + 0], 0.f));
            v.y = f2tf_f(fmaxf(acc[i][1] + sm[OFF_B0 + c0 + 1], 0.f));
            v.z = f2tf_f(fmaxf(acc[i][2] + sm[OFF_B0 + c0 + 2], 0.f));
            v.w = f2tf_f(fmaxf(acc[i][3] + sm[OFF_B0 + c0 + 3], 0.f));
            *(float4*)(ownS + (r0 + i) * LDA + c0) = v;
        }
    }
    __syncthreads();

    // ---------- Phase 3: u = own_e @ (Wq Wk^T); stage state2 (fp32) ----------
    wr4(pw, wS, tid);                     // Wqk -> wS (tf32)
    for (int i = tid; i < 3584; i += THREADS) {
        int m = i / 56, r2 = i % 56;
        aS[m * LDA + (r2 / 7) * 8 + (r2 % 7)] = state2[(size_t)row0 * 56 + i];
    }
    __syncthreads();
    {
        float acc[4][4] = {};
        mma_k64(ownS, wS, R0, C0, gid, tig, acc);
        epi_store(acc, e1S, nullptr, false, false, R0, C0, gid, tig);  // u fp32 -> e1S
    }
    // mask[m][n]
    for (int t = tid; t < 512; t += THREADS) {
        int m = t >> 3, n = t & 7;
        float s = 0.f;
#pragma unroll
        for (int f = 0; f < 7; ++f) s += aS[m * LDA + n * 8 + f];
        sm[OFF_MK + t] = ((s * (1.f / 7.f)) != 0.f) ? 1.f : 0.f;
    }
    __syncthreads();

    // pull u into registers (score mapping: thread -> row m, 16-col chunk q)
    const int sm_m = tid >> 2, sm_q = tid & 3;
    float4 u0 = *(const float4*)(e1S + sm_m * LDA + sm_q * 16 + 0);
    float4 u1 = *(const float4*)(e1S + sm_m * LDA + sm_q * 16 + 4);
    float4 u2 = *(const float4*)(e1S + sm_m * LDA + sm_q * 16 + 8);
    float4 u3 = *(const float4*)(e1S + sm_m * LDA + sm_q * 16 + 12);
    pf4(pw, Ws2, 64, tid);
    wr4(pw, wS, tid);                     // Ws2 -> wS (tf32)
    __syncthreads();

    // ---------- Phase 4: neighbor stack (e1 scalar fp32, e2 MMA -> g_e2 fp32) ----------
    for (int n = 0; n < 8; ++n) {
        {   // e1 = relu(state2_n @ Ws1 + bs1), store tf32 for e2 MMA
            float acc[4][4] = {};
            mm_small<7, 64>(aS + n * 8, sm + OFF_WS1, r0, c0, acc);
#pragma unroll
            for (int i = 0; i < 4; ++i) {
                float4 v;
                v.x = f2tf_f(fmaxf(acc[i][0] + sm[OFF_BS1 + c0 + 0], 0.f));
                v.y = f2tf_f(fmaxf(acc[i][1] + sm[OFF_BS1 + c0 + 1], 0.f));
                v.z = f2tf_f(fmaxf(acc[i][2] + sm[OFF_BS1 + c0 + 2], 0.f));
                v.w = f2tf_f(fmaxf(acc[i][3] + sm[OFF_BS1 + c0 + 3], 0.f));
                *(float4*)(e1S + (r0 + i) * LDA + c0) = v;
            }
        }
        __syncthreads();
        {   // e2 = relu(e1 @ Ws2 + bs2) -> g_e2 (fp32 exact)
            float acc[4][4] = {};
            mma_k64(e1S, wS, R0, C0, gid, tig, acc);
#pragma unroll
            for (int j = 0; j < 4; ++j) {
                int cc = C0 + 8 * j + 2 * tig;
                float bx = sm[OFF_BS2 + cc], by = sm[OFF_BS2 + cc + 1];
                float2 v0 = make_float2(fmaxf(acc[j][0] + bx, 0.f), fmaxf(acc[j][1] + by, 0.f));
                float2 v1 = make_float2(fmaxf(acc[j][2] + bx, 0.f), fmaxf(acc[j][3] + by, 0.f));
                *(float2*)(g_e2 + ((size_t)(row0 + R0 + gid) * 8 + n) * 64 + cc) = v0;
                *(float2*)(g_e2 + ((size_t)(row0 + R0 + gid + 8) * 8 + n) * 64 + cc) = v1;
            }
        }
        __syncthreads();
    }

    // ---------- scores: sc[m][n] = e2[m][n] . u[m] ----------
    for (int n = 0; n < 8; ++n) {
        const float* p = g_e2 + ((size_t)(row0 + sm_m) * 8 + n) * 64 + sm_q * 16;
        float4 x0 = *(const float4*)(p + 0), x1 = *(const float4*)(p + 4);
        float4 x2 = *(const float4*)(p + 8), x3 = *(const float4*)(p + 12);
        float s = x0.x * u0.x + x0.y * u0.y + x0.z * u0.z + x0.w * u0.w
                + x1.x * u1.x + x1.y * u1.y + x1.z * u1.z + x1.w * u1.w
                + x2.x * u2.x + x2.y * u2.y + x2.z * u2.z + x2.w * u2.w
                + x3.x * u3.x + x3.y * u3.y + x3.z * u3.z + x3.w * u3.w;
        s += __shfl_xor_sync(0xffffffffu, s, 1);
        s += __shfl_xor_sync(0xffffffffu, s, 2);
        if (sm_q == 0) sm[OFF_SC + sm_m * 8 + n] = s;
    }
    __syncthreads();

    // ---------- Phase 5: masked softmax ----------
    if (tid < 64) {
        float s8[8], e8[8], mx = -3.4e38f, sum = 0.f;
#pragma unroll
        for (int n = 0; n < 8; ++n) {
            s8[n] = sm[OFF_SC + tid * 8 + n] * 0.125f;
            if (sm[OFF_MK + tid * 8 + n] != 0.f) mx = fmaxf(mx, s8[n]);
        }
#pragma unroll
        for (int n = 0; n < 8; ++n) {
            e8[n] = (sm[OFF_MK + tid * 8 + n] != 0.f) ? expf(s8[n] - mx) : 0.f;
            sum += e8[n];
        }
        float inv = 1.f / sum;
#pragma unroll
        for (int n = 0; n < 8; ++n) sm[OFF_AL + tid * 8 + n] = e8[n] * inv;
    }
    __syncthreads();

    // ---------- Phase 6: ebar = sum_n alpha_n e2_n -> e1S (tf32); v_att = ebar @ Wv ----------
    pf4(pw, Wv, 64, tid);                 // prefetch Wv behind ebar compute
    {
        float eb[16] = {};
#pragma unroll
        for (int n = 0; n < 8; ++n) {
            float a = sm[OFF_AL + sm_m * 8 + n];
            const float* p = g_e2 + ((size_t)(row0 + sm_m) * 8 + n) * 64 + sm_q * 16;
#pragma unroll
            for (int h = 0; h < 4; ++h) {
                float4 v = *(const float4*)(p + h * 4);
                eb[h * 4 + 0] = fmaf(a, v.x, eb[h * 4 + 0]);
                eb[h * 4 + 1] = fmaf(a, v.y, eb[h * 4 + 1]);
                eb[h * 4 + 2] = fmaf(a, v.z, eb[h * 4 + 2]);
                eb[h * 4 + 3] = fmaf(a, v.w, eb[h * 4 + 3]);
            }
        }
#pragma unroll
        for (int h = 0; h < 4; ++h)
            *(float4*)(e1S + sm_m * LDA + sm_q * 16 + h * 4) =
                make_float4(f2tf_f(eb[h * 4 + 0]), f2tf_f(eb[h * 4 + 1]),
                            f2tf_f(eb[h * 4 + 2]), f2tf_f(eb[h * 4 + 3]));
    }
    wr4(pw, wS, tid);                     // Wv -> wS (tf32)
    __syncthreads();
    {
        float acc[4][4] = {};
        mma_k64(e1S, wS, R0, C0, gid, tig, acc);
        epi_store(acc, aS, nullptr, false, true, R0, C0, gid, tig);   // v_att tf32 -> aS
    }

    // ---------- Phase 7+8: head GEMMs with register-prefetched weight stages ----------
    // stages 0..5: Wc1[half=st/3][seg=st%3]; stages 6..9: Wc2[half=(st-6)/2][seg=(st-6)%2]
    {
        const float* srcs[3] = { ownS, envS, aS };
        // stage 0 prefetch
        pf4(pw, Wc1, 128, tid);
        int st = 0;
        // Phase 7: h1
        for (int half = 0; half < 2; ++half) {
            float acc[4][4] = {};
            for (int seg = 0; seg < 3; ++seg) {
                __syncthreads();
                wr4(pw, wS, tid);
                __syncthreads();
                ++st;
                if (st < 6)
                    pf4(pw, Wc1 + (st % 3) * 8192 + (st / 3) * 64, 128, tid);
                else if (st < 10)
                    pf4(pw, Wc2 + ((st - 6) % 2) * 8192 + ((st - 6) / 2) * 64, 128, tid);
                mma_k64(srcs[seg], wS, R0, C0, gid, tig, acc);
            }
            epi_store(acc, half ? ownS : e1S, sm + OFF_BC1 + half * 64, true, true,
                      R0, C0, gid, tig);                  // h1 lo->e1S, hi->ownS (tf32)
        }
        // Phase 8: h2 (fp32 out for scalar phase 9)
        for (int half = 0; half < 2; ++half) {
            float acc[4][4] = {};
            for (int seg = 0; seg < 2; ++seg) {
                __syncthreads();
                wr4(pw, wS, tid);
                __syncthreads();
                ++st;
                if (st < 10)
                    pf4(pw, Wc2 + ((st - 6) % 2) * 8192 + ((st - 6) / 2) * 64, 128, tid);
                mma_k64(seg ? ownS : e1S, wS, R0, C0, gid, tig, acc);
            }
            epi_store(acc, half ? aS : envS, sm + OFF_BC2 + half * 64, true, false,
                      R0, C0, gid, tig);                  // h2 lo->envS, hi->aS (fp32)
        }
    }
    __syncthreads();

    // ---------- Phase 9: out = tanh(h2 @ Wc3 + bc3), fp32 scalar ----------
    if (tid < 64) {
        float o0 = sm[OFF_BC3 + 0], o1 = sm[OFF_BC3 + 1];
#pragma unroll 8
        for (int k = 0; k < 64; ++k) {
            int kk = (k + tid) & 63;
            float hlo = envS[tid * LDA + kk];
            float hhi = aS[tid * LDA + kk];
            o0 = fmaf(hlo, sm[OFF_WC3 + kk * 2 + 0], o0);
            o1 = fmaf(hlo, sm[OFF_WC3 + kk * 2 + 1], o1);
            o0 = fmaf(hhi, sm[OFF_WC3 + (64 + kk) * 2 + 0], o0);
            o1 = fmaf(hhi, sm[OFF_WC3 + (64 + kk) * 2 + 1], o1);
        }
        out[(size_t)(row0 + tid) * 2 + 0] = tanhf(o0);
        out[(size_t)(row0 + tid) * 2 + 1] = tanhf(o1);
    }
}

extern "C" void kernel_launch(void* const* d_in, const int* in_sizes, int n_in,
                              void* d_out, int out_size)
{
    const float* state0 = (const float*)d_in[0];
    const float* state1 = (const float*)d_in[1];
    const float* state2 = (const float*)d_in[2];
    const float* W0  = (const float*)d_in[3];
    const float* b0  = (const float*)d_in[4];
    const float* Wg  = (const float*)d_in[5];
    const float* bg  = (const float*)d_in[6];
    const float* Ws1 = (const float*)d_in[7];
    const float* bs1 = (const float*)d_in[8];
    const float* Ws2 = (const float*)d_in[9];
    const float* bs2 = (const float*)d_in[10];
    const float* Wq  = (const float*)d_in[11];
    const float* Wk  = (const float*)d_in[12];
    const float* Wv  = (const float*)d_in[13];
    const float* Wc1 = (const float*)d_in[14];
    const float* bc1 = (const float*)d_in[15];
    const float* Wc2 = (const float*)d_in[16];
    const float* bc2 = (const float*)d_in[17];
    const float* Wc3 = (const float*)d_in[18];
    const float* bc3 = (const float*)d_in[19];
    float* out = (float*)d_out;

    cudaFuncSetAttribute(actor_kernel,
                         cudaFuncAttributeMaxDynamicSharedMemorySize, SMEM_BYTES);

    wqk_kernel<<<16, 256>>>(Wq, Wk);
    actor_kernel<<<65536 / ROWS, THREADS, SMEM_BYTES>>>(
        state0, state1, state2, W0, b0, Wg, bg, Ws1, bs1, Ws2, bs2,
        Wv, Wc1, bc1, Wc2, bc2, Wc3, bc3, out);
}

// round 14
// speedup vs baseline: 1.1635x; 1.1635x over previous
#include <cuda_runtime.h>
#include <math.h>
#include <stdint.h>

#define THREADS 256
#define ROWS 64
#define LDA 68
#define WLD 72

// ---- shared memory layout (float offsets) ----
#define OFF_ENV 0              // 64 x 68
#define OFF_OWN 4352
#define OFF_A   8704
#define OFF_E1  13056
#define OFF_W   17408          // 64 x 72
#define OFF_B0  22016
#define OFF_BG  22080
#define OFF_BS1 22144
#define OFF_BS2 22208
#define OFF_BC1 22272          // 128
#define OFF_BC2 22400          // 128
#define OFF_BC3 22528          // 4
#define OFF_WS1 22532          // 7x64
#define OFF_WC3 22980          // 128x2
#define OFF_SC  23236          // 64x8
#define OFF_AL  23748          // 64x8
#define OFF_MK  24260          // 64x8
#define SMEM_FLOATS 24772
#define SMEM_BYTES (SMEM_FLOATS * 4)

__device__ float g_e2[(size_t)65536 * 8 * 64];   // e2 spill, L2-hot per CTA
__device__ float g_Wqk[64 * 64];                 // M = Wq @ Wk^T

// round to tf32, keep as fp32 bit pattern
__device__ __forceinline__ float f2tf_f(float x) {
    uint32_t r;
    asm("cvt.rna.tf32.f32 %0, %1;" : "=r"(r) : "f"(x));
    return __uint_as_float(r);
}

__device__ __forceinline__ void mma8(float (&c)[4], uint32_t a0, uint32_t a1,
                                     uint32_t a2, uint32_t a3,
                                     uint32_t b0, uint32_t b1)
{
    asm volatile("mma.sync.aligned.m16n8k8.row.col.f32.tf32.tf32.f32 "
                 "{%0,%1,%2,%3}, {%4,%5,%6,%7}, {%8,%9}, {%0,%1,%2,%3};"
                 : "+f"(c[0]), "+f"(c[1]), "+f"(c[2]), "+f"(c[3])
                 : "r"(a0), "r"(a1), "r"(a2), "r"(a3), "r"(b0), "r"(b1));
}

// warp-level 64x64x64 MMA; operands are PRE-CONVERTED tf32 bits (no cvt here)
__device__ __forceinline__ void mma_k64(const float* __restrict__ A,
                                        const float* __restrict__ W,
                                        int R0, int C0, int gid, int tig,
                                        float (&c)[4][4])
{
#pragma unroll
    for (int kt = 0; kt < 8; ++kt) {
        const float* Ap = A + (R0 + gid) * LDA + kt * 8 + tig;
        uint32_t a0 = __float_as_uint(Ap[0]);
        uint32_t a1 = __float_as_uint(Ap[8 * LDA]);
        uint32_t a2 = __float_as_uint(Ap[4]);
        uint32_t a3 = __float_as_uint(Ap[8 * LDA + 4]);
        const float* Wp = W + (kt * 8 + tig) * WLD + C0 + gid;
#pragma unroll
        for (int j = 0; j < 4; ++j) {
            uint32_t b0 = __float_as_uint(Wp[8 * j]);
            uint32_t b1 = __float_as_uint(Wp[4 * WLD + 8 * j]);
            mma8(c[j], a0, a1, a2, a3, b0, b1);
        }
    }
}

// epilogue: optional bias + relu; cvt -> store tf32 bits for downstream MMA
__device__ __forceinline__ void epi_store(float (&c)[4][4], float* dst,
                                          const float* bias, bool relu, bool cvt,
                                          int R0, int C0, int gid, int tig)
{
#pragma unroll
    for (int j = 0; j < 4; ++j) {
        int cc = C0 + 8 * j + 2 * tig;
        float bx = bias ? bias[cc] : 0.f;
        float by = bias ? bias[cc + 1] : 0.f;
        float2 v0 = make_float2(c[j][0] + bx, c[j][1] + by);
        float2 v1 = make_float2(c[j][2] + bx, c[j][3] + by);
        if (relu) {
            v0.x = fmaxf(v0.x, 0.f); v0.y = fmaxf(v0.y, 0.f);
            v1.x = fmaxf(v1.x, 0.f); v1.y = fmaxf(v1.y, 0.f);
        }
        if (cvt) {
            v0.x = f2tf_f(v0.x); v0.y = f2tf_f(v0.y);
            v1.x = f2tf_f(v1.x); v1.y = f2tf_f(v1.y);
        }
        *(float2*)(dst + (R0 + gid) * LDA + cc) = v0;
        *(float2*)(dst + (R0 + gid + 8) * LDA + cc) = v1;
    }
}

// scalar microkernel for tiny-K GEMMs (K=6,7). A leading dim LDA. fp32 exact.
template<int K, int WL>
__device__ __forceinline__ void mm_small(const float* __restrict__ A,
                                         const float* __restrict__ W,
                                         int r0, int c0, float (&acc)[4][4])
{
#pragma unroll
    for (int k = 0; k < K; ++k) {
        float a0 = A[(r0 + 0) * LDA + k];
        float a1 = A[(r0 + 1) * LDA + k];
        float a2 = A[(r0 + 2) * LDA + k];
        float a3 = A[(r0 + 3) * LDA + k];
        float4 b = *(const float4*)(W + k * WL + c0);
        acc[0][0] = fmaf(a0, b.x, acc[0][0]); acc[0][1] = fmaf(a0, b.y, acc[0][1]);
        acc[0][2] = fmaf(a0, b.z, acc[0][2]); acc[0][3] = fmaf(a0, b.w, acc[0][3]);
        acc[1][0] = fmaf(a1, b.x, acc[1][0]); acc[1][1] = fmaf(a1, b.y, acc[1][1]);
        acc[1][2] = fmaf(a1, b.z, acc[1][2]); acc[1][3] = fmaf(a1, b.w, acc[1][3]);
        acc[2][0] = fmaf(a2, b.x, acc[2][0]); acc[2][1] = fmaf(a2, b.y, acc[2][1]);
        acc[2][2] = fmaf(a2, b.z, acc[2][2]); acc[2][3] = fmaf(a2, b.w, acc[2][3]);
        acc[3][0] = fmaf(a3, b.x, acc[3][0]); acc[3][1] = fmaf(a3, b.y, acc[3][1]);
        acc[3][2] = fmaf(a3, b.z, acc[3][2]); acc[3][3] = fmaf(a3, b.w, acc[3][3]);
    }
}

__global__ void wqk_kernel(const float* __restrict__ Wq, const float* __restrict__ Wk)
{
    int idx = blockIdx.x * 256 + threadIdx.x;
    int c = idx >> 6, d = idx & 63;
    float s = 0.f;
#pragma unroll 8
    for (int j = 0; j < 64; ++j)
        s = fmaf(Wq[c * 64 + j], Wk[d * 64 + j], s);
    g_Wqk[idx] = s;
}

__global__ void __launch_bounds__(THREADS, 2)
actor_kernel(const float* __restrict__ state0, const float* __restrict__ state1,
             const float* __restrict__ state2,
             const float* __restrict__ W0,  const float* __restrict__ b0,
             const float* __restrict__ Wg,  const float* __restrict__ bg,
             const float* __restrict__ Ws1, const float* __restrict__ bs1,
             const float* __restrict__ Ws2, const float* __restrict__ bs2,
             const float* __restrict__ Wv,
             const float* __restrict__ Wc1, const float* __restrict__ bc1,
             const float* __restrict__ Wc2, const float* __restrict__ bc2,
             const float* __restrict__ Wc3, const float* __restrict__ bc3,
             float* __restrict__ out)
{
    extern __shared__ float sm[];
    const int tid  = threadIdx.x;
    const int lane = tid & 31, wid = tid >> 5;
    const int gid = lane >> 2, tig = lane & 3;
    const int R0 = (wid >> 1) * 16, C0 = (wid & 1) * 32;
    const int tx = tid & 15, ty = tid >> 4;       // scalar-path mapping
    const int r0 = ty * 4, c0 = tx * 4;
    const int row0 = blockIdx.x * ROWS;

    float* envS = sm + OFF_ENV;
    float* ownS = sm + OFF_OWN;
    float* aS   = sm + OFF_A;
    float* e1S  = sm + OFF_E1;
    float* wS   = sm + OFF_W;

    // constants
    if (tid < 64) {
        sm[OFF_B0 + tid]  = b0[tid];  sm[OFF_BG + tid]  = bg[tid];
        sm[OFF_BS1 + tid] = bs1[tid]; sm[OFF_BS2 + tid] = bs2[tid];
    }
    if (tid < 128) { sm[OFF_BC1 + tid] = bc1[tid]; sm[OFF_BC2 + tid] = bc2[tid]; }
    if (tid < 2)   { sm[OFF_BC3 + tid] = bc3[tid]; }
    for (int i = tid; i < 448; i += THREADS) sm[OFF_WS1 + i] = Ws1[i];
    for (int i = tid; i < 256; i += THREADS) sm[OFF_WC3 + i] = Wc3[i];

    // ---------- Phase 1: env_e = relu(state1 @ Wg + bg), K=1024, tf32 MMA ----------
    {
        float acc[4][4] = {};
        float4 ra[4], rw[4];
#pragma unroll
        for (int j = 0; j < 4; ++j) {
            int i = tid + j * 256, m = i >> 4, c4 = i & 15;
            ra[j] = *(const float4*)(state1 + (size_t)(row0 + m) * 1024 + c4 * 4);
            rw[j] = *(const float4*)(Wg + (size_t)m * 64 + c4 * 4);
        }
        for (int ch = 0; ch < 16; ++ch) {
#pragma unroll
            for (int j = 0; j < 4; ++j) {
                int i = tid + j * 256, m = i >> 4, c4 = i & 15;
                *(float4*)(aS + m * LDA + c4 * 4) =
                    make_float4(f2tf_f(ra[j].x), f2tf_f(ra[j].y),
                                f2tf_f(ra[j].z), f2tf_f(ra[j].w));
                *(float4*)(wS + m * WLD + c4 * 4) =
                    make_float4(f2tf_f(rw[j].x), f2tf_f(rw[j].y),
                                f2tf_f(rw[j].z), f2tf_f(rw[j].w));
            }
            __syncthreads();
            if (ch + 1 < 16) {
                int kk = (ch + 1) * 64;
#pragma unroll
                for (int j = 0; j < 4; ++j) {
                    int i = tid + j * 256, m = i >> 4, c4 = i & 15;
                    ra[j] = *(const float4*)(state1 + (size_t)(row0 + m) * 1024 + kk + c4 * 4);
                    rw[j] = *(const float4*)(Wg + (size_t)(kk + m) * 64 + c4 * 4);
                }
            }
            mma_k64(aS, wS, R0, C0, gid, tig, acc);
            __syncthreads();
        }
        epi_store(acc, envS, sm + OFF_BG, true, true, R0, C0, gid, tig);
    }

    // ---------- Phase 2: own_e = relu(state0 @ W0 + b0), K=6, scalar fp32 ----------
    for (int i = tid; i < 384; i += THREADS)
        aS[(i / 6) * LDA + (i % 6)] = state0[(size_t)row0 * 6 + i];
    for (int i = tid; i < 384; i += THREADS)
        wS[(i >> 6) * WLD + (i & 63)] = W0[i];
    __syncthreads();
    {
        float acc[4][4] = {};
        mm_small<6, WLD>(aS, wS, r0, c0, acc);
#pragma unroll
        for (int i = 0; i < 4; ++i) {
            float4 v;
            v.x = f2tf_f(fmaxf(acc[i][0] + sm[OFF_B0 + c0 + 0], 0.f));
            v.y = f2tf_f(fmaxf(acc[i][1] + sm[OFF_B0 + c0 + 1], 0.f));
            v.z = f2tf_f(fmaxf(acc[i][2] + sm[OFF_B0 + c0 + 2], 0.f));
            v.w = f2tf_f(fmaxf(acc[i][3] + sm[OFF_B0 + c0 + 3], 0.f));
            *(float4*)(ownS + (r0 + i) * LDA + c0) = v;
        }
    }
    __syncthreads();

    // ---------- Phase 3: u = own_e @ (Wq Wk^T); stage state2 (fp32) ----------
    for (int i = tid; i < 4096; i += THREADS)
        wS[(i >> 6) * WLD + (i & 63)] = f2tf_f(g_Wqk[i]);
    for (int i = tid; i < 3584; i += THREADS) {
        int m = i / 56, r2 = i % 56;
        aS[m * LDA + (r2 / 7) * 8 + (r2 % 7)] = state2[(size_t)row0 * 56 + i];
    }
    __syncthreads();
    {
        float acc[4][4] = {};
        mma_k64(ownS, wS, R0, C0, gid, tig, acc);
        epi_store(acc, e1S, nullptr, false, false, R0, C0, gid, tig);  // u fp32 -> e1S
    }
    // mask[m][n]
    for (int t = tid; t < 512; t += THREADS) {
        int m = t >> 3, n = t & 7;
        float s = 0.f;
#pragma unroll
        for (int f = 0; f < 7; ++f) s += aS[m * LDA + n * 8 + f];
        sm[OFF_MK + t] = ((s * (1.f / 7.f)) != 0.f) ? 1.f : 0.f;
    }
    __syncthreads();

    // pull u into registers (score mapping: thread -> row m, 16-col chunk q)
    const int sm_m = tid >> 2, sm_q = tid & 3;
    float4 u0 = *(const float4*)(e1S + sm_m * LDA + sm_q * 16 + 0);
    float4 u1 = *(const float4*)(e1S + sm_m * LDA + sm_q * 16 + 4);
    float4 u2 = *(const float4*)(e1S + sm_m * LDA + sm_q * 16 + 8);
    float4 u3 = *(const float4*)(e1S + sm_m * LDA + sm_q * 16 + 12);
    __syncthreads();
    // load Ws2 (tf32) for the neighbor stack
    for (int i = tid; i < 4096; i += THREADS)
        wS[(i >> 6) * WLD + (i & 63)] = f2tf_f(Ws2[i]);
    __syncthreads();

    // ---------- Phase 4: neighbor stack (e1 scalar fp32 -> tf32, e2 MMA -> g_e2 fp32) ----------
    for (int n = 0; n < 8; ++n) {
        {   // e1 = relu(state2_n @ Ws1 + bs1), store tf32 for e2 MMA
            float acc[4][4] = {};
            mm_small<7, 64>(aS + n * 8, sm + OFF_WS1, r0, c0, acc);
#pragma unroll
            for (int i = 0; i < 4; ++i) {
                float4 v;
                v.x = f2tf_f(fmaxf(acc[i][0] + sm[OFF_BS1 + c0 + 0], 0.f));
                v.y = f2tf_f(fmaxf(acc[i][1] + sm[OFF_BS1 + c0 + 1], 0.f));
                v.z = f2tf_f(fmaxf(acc[i][2] + sm[OFF_BS1 + c0 + 2], 0.f));
                v.w = f2tf_f(fmaxf(acc[i][3] + sm[OFF_BS1 + c0 + 3], 0.f));
                *(float4*)(e1S + (r0 + i) * LDA + c0) = v;
            }
        }
        __syncthreads();
        {   // e2 = relu(e1 @ Ws2 + bs2) -> g_e2 (fp32 exact)
            float acc[4][4] = {};
            mma_k64(e1S, wS, R0, C0, gid, tig, acc);
#pragma unroll
            for (int j = 0; j < 4; ++j) {
                int cc = C0 + 8 * j + 2 * tig;
                float bx = sm[OFF_BS2 + cc], by = sm[OFF_BS2 + cc + 1];
                float2 v0 = make_float2(fmaxf(acc[j][0] + bx, 0.f), fmaxf(acc[j][1] + by, 0.f));
                float2 v1 = make_float2(fmaxf(acc[j][2] + bx, 0.f), fmaxf(acc[j][3] + by, 0.f));
                *(float2*)(g_e2 + ((size_t)(row0 + R0 + gid) * 8 + n) * 64 + cc) = v0;
                *(float2*)(g_e2 + ((size_t)(row0 + R0 + gid + 8) * 8 + n) * 64 + cc) = v1;
            }
        }
        __syncthreads();
    }

    // ---------- scores: sc[m][n] = e2[m][n] . u[m] ----------
    for (int n = 0; n < 8; ++n) {
        const float* p = g_e2 + ((size_t)(row0 + sm_m) * 8 + n) * 64 + sm_q * 16;
        float4 x0 = *(const float4*)(p + 0), x1 = *(const float4*)(p + 4);
        float4 x2 = *(const float4*)(p + 8), x3 = *(const float4*)(p + 12);
        float s = x0.x * u0.x + x0.y * u0.y + x0.z * u0.z + x0.w * u0.w
                + x1.x * u1.x + x1.y * u1.y + x1.z * u1.z + x1.w * u1.w
                + x2.x * u2.x + x2.y * u2.y + x2.z * u2.z + x2.w * u2.w
                + x3.x * u3.x + x3.y * u3.y + x3.z * u3.z + x3.w * u3.w;
        s += __shfl_xor_sync(0xffffffffu, s, 1);
        s += __shfl_xor_sync(0xffffffffu, s, 2);
        if (sm_q == 0) sm[OFF_SC + sm_m * 8 + n] = s;
    }
    __syncthreads();

    // ---------- Phase 5: masked softmax ----------
    if (tid < 64) {
        float s8[8], e8[8], mx = -3.4e38f, sum = 0.f;
#pragma unroll
        for (int n = 0; n < 8; ++n) {
            s8[n] = sm[OFF_SC + tid * 8 + n] * 0.125f;
            if (sm[OFF_MK + tid * 8 + n] != 0.f) mx = fmaxf(mx, s8[n]);
        }
#pragma unroll
        for (int n = 0; n < 8; ++n) {
            e8[n] = (sm[OFF_MK + tid * 8 + n] != 0.f) ? expf(s8[n] - mx) : 0.f;
            sum += e8[n];
        }
        float inv = 1.f / sum;
#pragma unroll
        for (int n = 0; n < 8; ++n) sm[OFF_AL + tid * 8 + n] = e8[n] * inv;
    }
    __syncthreads();

    // ---------- Phase 6: ebar = sum_n alpha_n e2_n -> e1S (tf32); v_att = ebar @ Wv ----------
    {
        float eb[16] = {};
#pragma unroll
        for (int n = 0; n < 8; ++n) {
            float a = sm[OFF_AL + sm_m * 8 + n];
            const float* p = g_e2 + ((size_t)(row0 + sm_m) * 8 + n) * 64 + sm_q * 16;
#pragma unroll
            for (int h = 0; h < 4; ++h) {
                float4 v = *(const float4*)(p + h * 4);
                eb[h * 4 + 0] = fmaf(a, v.x, eb[h * 4 + 0]);
                eb[h * 4 + 1] = fmaf(a, v.y, eb[h * 4 + 1]);
                eb[h * 4 + 2] = fmaf(a, v.z, eb[h * 4 + 2]);
                eb[h * 4 + 3] = fmaf(a, v.w, eb[h * 4 + 3]);
            }
        }
#pragma unroll
        for (int h = 0; h < 4; ++h)
            *(float4*)(e1S + sm_m * LDA + sm_q * 16 + h * 4) =
                make_float4(f2tf_f(eb[h * 4 + 0]), f2tf_f(eb[h * 4 + 1]),
                            f2tf_f(eb[h * 4 + 2]), f2tf_f(eb[h * 4 + 3]));
    }
    __syncthreads();
    for (int i = tid; i < 4096; i += THREADS)
        wS[(i >> 6) * WLD + (i & 63)] = f2tf_f(Wv[i]);
    __syncthreads();
    {
        float acc[4][4] = {};
        mma_k64(e1S, wS, R0, C0, gid, tig, acc);
        epi_store(acc, aS, nullptr, false, true, R0, C0, gid, tig);   // v_att tf32 -> aS
    }

    // ---------- Phase 7: h1 = relu([own env vatt] @ Wc1 + bc1) ----------
    {
        const float* srcs[3] = { ownS, envS, aS };
        for (int half = 0; half < 2; ++half) {
            float acc[4][4] = {};
            for (int seg = 0; seg < 3; ++seg) {
                __syncthreads();
                for (int i = tid; i < 4096; i += THREADS)
                    wS[(i >> 6) * WLD + (i & 63)] =
                        f2tf_f(Wc1[(size_t)(seg * 64 + (i >> 6)) * 128 + half * 64 + (i & 63)]);
                __syncthreads();
                mma_k64(srcs[seg], wS, R0, C0, gid, tig, acc);
            }
            __syncthreads();
            epi_store(acc, half ? ownS : e1S, sm + OFF_BC1 + half * 64, true, true,
                      R0, C0, gid, tig);                  // h1 lo->e1S, hi->ownS (tf32)
        }
    }

    // ---------- Phase 8: h2 = relu(h1 @ Wc2 + bc2), fp32 out ----------
    for (int half = 0; half < 2; ++half) {
        float acc[4][4] = {};
        for (int seg = 0; seg < 2; ++seg) {
            __syncthreads();
            for (int i = tid; i < 4096; i += THREADS)
                wS[(i >> 6) * WLD + (i & 63)] =
                    f2tf_f(Wc2[(size_t)(seg * 64 + (i >> 6)) * 128 + half * 64 + (i & 63)]);
            __syncthreads();
            mma_k64(seg ? ownS : e1S, wS, R0, C0, gid, tig, acc);
        }
        __syncthreads();
        epi_store(acc, half ? aS : envS, sm + OFF_BC2 + half * 64, true, false,
                  R0, C0, gid, tig);                      // h2 lo->envS, hi->aS (fp32)
    }
    __syncthreads();

    // ---------- Phase 9: out = tanh(h2 @ Wc3 + bc3), fp32 scalar ----------
    if (tid < 64) {
        float o0 = sm[OFF_BC3 + 0], o1 = sm[OFF_BC3 + 1];
#pragma unroll 8
        for (int k = 0; k < 64; ++k) {
            int kk = (k + tid) & 63;
            float hlo = envS[tid * LDA + kk];
            float hhi = aS[tid * LDA + kk];
            o0 = fmaf(hlo, sm[OFF_WC3 + kk * 2 + 0], o0);
            o1 = fmaf(hlo, sm[OFF_WC3 + kk * 2 + 1], o1);
            o0 = fmaf(hhi, sm[OFF_WC3 + (64 + kk) * 2 + 0], o0);
            o1 = fmaf(hhi, sm[OFF_WC3 + (64 + kk) * 2 + 1], o1);
        }
        out[(size_t)(row0 + tid) * 2 + 0] = tanhf(o0);
        out[(size_t)(row0 + tid) * 2 + 1] = tanhf(o1);
    }
}

extern "C" void kernel_launch(void* const* d_in, const int* in_sizes, int n_in,
                              void* d_out, int out_size)
{
    const float* state0 = (const float*)d_in[0];
    const float* state1 = (const float*)d_in[1];
    const float* state2 = (const float*)d_in[2];
    const float* W0  = (const float*)d_in[3];
    const float* b0  = (const float*)d_in[4];
    const float* Wg  = (const float*)d_in[5];
    const float* bg  = (const float*)d_in[6];
    const float* Ws1 = (const float*)d_in[7];
    const float* bs1 = (const float*)d_in[8];
    const float* Ws2 = (const float*)d_in[9];
    const float* bs2 = (const float*)d_in[10];
    const float* Wq  = (const float*)d_in[11];
    const float* Wk  = (const float*)d_in[12];
    const float* Wv  = (const float*)d_in[13];
    const float* Wc1 = (const float*)d_in[14];
    const float* bc1 = (const float*)d_in[15];
    const float* Wc2 = (const float*)d_in[16];
    const float* bc2 = (const float*)d_in[17];
    const float* Wc3 = (const float*)d_in[18];
    const float* bc3 = (const float*)d_in[19];
    float* out = (float*)d_out;

    cudaFuncSetAttribute(actor_kernel,
                         cudaFuncAttributeMaxDynamicSharedMemorySize, SMEM_BYTES);

    wqk_kernel<<<16, 256>>>(Wq, Wk);
    actor_kernel<<<65536 / ROWS, THREADS, SMEM_BYTES>>>(
        state0, state1, state2, W0, b0, Wg, bg, Ws1, bs1, Ws2, bs2,
        Wv, Wc1, bc1, Wc2, bc2, Wc3, bc3, out);
}